// round 1
// baseline (speedup 1.0000x reference)
#include <cuda_runtime.h>

#define NB 8
#define CDIM 512
#define NHEADS 8
#define HD 64
#define NT 4096           // H*W = 64*64

// ---------------- scratch (device globals: alloc-free) ----------------
__device__ float g_qkvo[(size_t)NB * 2048 * NT];   // 268 MB
__device__ float g_lepe[(size_t)NB * CDIM * NT];   // 67 MB
__device__ float g_y   [(size_t)NB * CDIM * NT];   // 67 MB
__device__ float g_eff [NB * NHEADS * NT];
__device__ float g_kv  [NB * NHEADS * HD * HD];
__device__ float g_km  [NB * NHEADS * HD];

__device__ __forceinline__ float elu1(float x) { return x > 0.f ? x + 1.f : __expf(x); }

__device__ __forceinline__ float warpSum(float v) {
#pragma unroll
    for (int o = 16; o > 0; o >>= 1) v += __shfl_xor_sync(0xffffffffu, v, o);
    return v;
}
__device__ __forceinline__ float warpMax(float v) {
#pragma unroll
    for (int o = 16; o > 0; o >>= 1) v = fmaxf(v, __shfl_xor_sync(0xffffffffu, v, o));
    return v;
}

// ---------------- zero accumulators (must run every graph replay) ----------------
__global__ void zero_kernel() {
    int i = blockIdx.x * blockDim.x + threadIdx.x;
    if (i < NB * NHEADS * HD * HD) g_kv[i] = 0.f;
    if (i < NB * NHEADS * HD)      g_km[i] = 0.f;
}

// ---------------- batched GEMM: C[b] = A[M,K] @ X[b][K,N] + bias ----------------
// 128x128 tile, BK=16, 256 threads, 8x8 microtile. All dims divide evenly here.
__global__ void __launch_bounds__(256) gemm_bias_kernel(
    const float* __restrict__ A, const float* __restrict__ X,
    const float* __restrict__ bias, float* __restrict__ C,
    int M, int K, int N)
{
    const int b = blockIdx.z;
    const float* Xb = X + (size_t)b * K * N;
    float*       Cb = C + (size_t)b * M * N;
    const int m0 = blockIdx.y * 128, n0 = blockIdx.x * 128;

    __shared__ float As[16][128];
    __shared__ float Bs[16][128];

    const int tid = threadIdx.x;
    const int tx = tid & 15, ty = tid >> 4;

    float acc[8][8];
#pragma unroll
    for (int i = 0; i < 8; i++)
#pragma unroll
        for (int j = 0; j < 8; j++) acc[i][j] = 0.f;

    for (int k0 = 0; k0 < K; k0 += 16) {
#pragma unroll
        for (int l = 0; l < 2; l++) {
            int id = tid + l * 256;
            int ar = id >> 2;            // 0..127
            int ac = (id & 3) * 4;       // 0,4,8,12
            float4 av = *(const float4*)&A[(size_t)(m0 + ar) * K + k0 + ac];
            As[ac + 0][ar] = av.x; As[ac + 1][ar] = av.y;
            As[ac + 2][ar] = av.z; As[ac + 3][ar] = av.w;
        }
#pragma unroll
        for (int l = 0; l < 2; l++) {
            int id = tid + l * 256;
            int br = id >> 5;            // 0..15
            int bc = (id & 31) * 4;      // 0..124
            *(float4*)&Bs[br][bc] = *(const float4*)&Xb[(size_t)(k0 + br) * N + n0 + bc];
        }
        __syncthreads();
#pragma unroll
        for (int k = 0; k < 16; k++) {
            float a[8], bb[8];
#pragma unroll
            for (int i = 0; i < 8; i++) a[i] = As[k][ty * 8 + i];
#pragma unroll
            for (int j = 0; j < 8; j++) bb[j] = Bs[k][tx * 8 + j];
#pragma unroll
            for (int i = 0; i < 8; i++)
#pragma unroll
                for (int j = 0; j < 8; j++) acc[i][j] += a[i] * bb[j];
        }
        __syncthreads();
    }

#pragma unroll
    for (int i = 0; i < 8; i++) {
        int m = m0 + ty * 8 + i;
        float bv = bias[m];
        float4 v0 = make_float4(acc[i][0] + bv, acc[i][1] + bv, acc[i][2] + bv, acc[i][3] + bv);
        float4 v1 = make_float4(acc[i][4] + bv, acc[i][5] + bv, acc[i][6] + bv, acc[i][7] + bv);
        *(float4*)&Cb[(size_t)m * N + n0 + tx * 8 + 0] = v0;
        *(float4*)&Cb[(size_t)m * N + n0 + tx * 8 + 4] = v1;
    }
}

// ---------------- depthwise 5x5 conv on v channels -> g_lepe ----------------
__global__ void __launch_bounds__(256) conv_kernel(
    const float* __restrict__ w_lepe, const float* __restrict__ b_lepe)
{
    const int bc = blockIdx.x;
    const int b = bc >> 9, c = bc & 511;
    __shared__ float wsh[25];
    const int tid = threadIdx.x;
    if (tid < 25) wsh[tid] = w_lepe[c * 25 + tid];
    __syncthreads();

    const int y = blockIdx.y * 4 + (tid >> 6);
    const int xw = tid & 63;
    const float* Vp = g_qkvo + ((size_t)b * 2048 + 1024 + c) * NT;

    float acc = b_lepe[c];
#pragma unroll
    for (int i = 0; i < 5; i++) {
        int yy = y + i - 2;
        if (yy < 0 || yy >= 64) continue;
#pragma unroll
        for (int j = 0; j < 5; j++) {
            int xx = xw + j - 2;
            if (xx < 0 || xx >= 64) continue;
            acc += wsh[i * 5 + j] * Vp[yy * 64 + xx];
        }
    }
    g_lepe[((size_t)b * 512 + c) * NT + y * 64 + xw] = acc;
}

// ---------------- per (b,h): q_mean -> logits -> softmax -> g_eff ----------------
__global__ void __launch_bounds__(256) stats_kernel()
{
    const int bh = blockIdx.x;
    const int b = bh >> 3, h = bh & 7;
    const float* Q  = g_qkvo + ((size_t)b * 2048 +       h * 64) * NT;
    const float* Kp = g_qkvo + ((size_t)b * 2048 + 512 + h * 64) * NT;

    __shared__ float sqm[64];
    __shared__ float red[8];
    const int tid = threadIdx.x;
    const int lane = tid & 31, wid = tid >> 5;

    if (tid < 64) sqm[tid] = 0.f;
    __syncthreads();

    // q_mean sums (atomic into smem; 64 rows x 4096)
    for (int d = 0; d < 64; d++) {
        float p = 0.f;
#pragma unroll
        for (int i = 0; i < 16; i++) p += elu1(Q[(size_t)d * NT + tid + i * 256]);
        p = warpSum(p);
        if (lane == 0) atomicAdd(&sqm[d], p);
    }
    __syncthreads();

    // logits
    float l[16];
#pragma unroll
    for (int i = 0; i < 16; i++) l[i] = 0.f;
    for (int d = 0; d < 64; d++) {
        float km = sqm[d] * (1.f / NT);
#pragma unroll
        for (int i = 0; i < 16; i++) l[i] += km * elu1(Kp[(size_t)d * NT + tid + i * 256]);
    }
    float mx = -1e30f;
#pragma unroll
    for (int i = 0; i < 16; i++) { l[i] *= 0.125f; mx = fmaxf(mx, l[i]); }

    // block max
    mx = warpMax(mx);
    if (lane == 0) red[wid] = mx;
    __syncthreads();
    if (tid == 0) {
        float m = red[0];
        for (int w = 1; w < 8; w++) m = fmaxf(m, red[w]);
        red[0] = m;
    }
    __syncthreads();
    mx = red[0];
    __syncthreads();

    // block sum of exp
    float s = 0.f;
#pragma unroll
    for (int i = 0; i < 16; i++) s += __expf(l[i] - mx);
    s = warpSum(s);
    if (lane == 0) red[wid] = s;
    __syncthreads();
    if (tid == 0) {
        float ss = 0.f;
        for (int w = 0; w < 8; w++) ss += red[w];
        red[0] = ss;
    }
    __syncthreads();
    const float inv = 1.f / red[0];

#pragma unroll
    for (int i = 0; i < 16; i++)
        g_eff[bh * NT + tid + i * 256] = __expf(l[i] - mx) * inv;
}

// ---------------- kv[d,e] = sum_t rope(k*eff)[t,d]*v[t,e];  km[d] = sum_t k*eff ----------------
__global__ void __launch_bounds__(256) kv_kernel(
    const float* __restrict__ sinp, const float* __restrict__ cosp)
{
    const int bh = blockIdx.x;
    const int b = bh >> 3, h = bh & 7;
    const int chunk = blockIdx.y;   // 8 chunks of 512 t
    const float* Kp  = g_qkvo + ((size_t)b * 2048 +  512 + h * 64) * NT;
    const float* Vp  = g_qkvo + ((size_t)b * 2048 + 1024 + h * 64) * NT;
    const float* eff = g_eff + bh * NT;

    __shared__ float sk[64][65];   // [t][d]
    __shared__ float sv[64][65];   // [t][e]

    const int tid = threadIdx.x;
    const int ttl = tid & 63;      // t within tile (consecutive across threads -> coalesced)
    const int drow = tid >> 6;     // 0..3
    const int d0 = (tid & 15) * 4, e0 = (tid >> 4) * 4;

    float acc[4][4];
#pragma unroll
    for (int i = 0; i < 4; i++)
#pragma unroll
        for (int j = 0; j < 4; j++) acc[i][j] = 0.f;
    float kmacc = 0.f;

    for (int tile = 0; tile < 8; tile++) {
        const int t0 = chunk * 512 + tile * 64;
        const float effv = eff[t0 + ttl];
#pragma unroll
        for (int r = 0; r < 16; r++) {
            int d = drow + r * 4;
            sk[ttl][d] = elu1(Kp[(size_t)d * NT + t0 + ttl]) * effv;
            sv[ttl][d] = Vp[(size_t)d * NT + t0 + ttl];
        }
        __syncthreads();

        // kmean partial (raw k*eff) -- read-only phase
        if (tid < 64) {
#pragma unroll 8
            for (int tt = 0; tt < 64; tt++) kmacc += sk[tt][tid];
        }
        // rope into registers (read-only phase)
        float r0[8], r1[8];
        const int t = t0 + ttl;
#pragma unroll
        for (int r = 0; r < 8; r++) {
            int pr = drow + r * 4;          // pair id 0..31
            int d = 2 * pr;
            float a  = sk[ttl][d];
            float bb = sk[ttl][d + 1];
            float c0 = cosp[t * 64 + d],     s0 = sinp[t * 64 + d];
            float c1 = cosp[t * 64 + d + 1], s1 = sinp[t * 64 + d + 1];
            r0[r] = a * c0 - bb * s0;
            r1[r] = bb * c1 + a * s1;
        }
        __syncthreads();
#pragma unroll
        for (int r = 0; r < 8; r++) {
            int d = 2 * (drow + r * 4);
            sk[ttl][d]     = r0[r];
            sk[ttl][d + 1] = r1[r];
        }
        __syncthreads();

        // accumulate kv outer products
#pragma unroll 4
        for (int tt = 0; tt < 64; tt++) {
            float kk[4], vv[4];
#pragma unroll
            for (int j = 0; j < 4; j++) { kk[j] = sk[tt][d0 + j]; vv[j] = sv[tt][e0 + j]; }
#pragma unroll
            for (int i = 0; i < 4; i++)
#pragma unroll
                for (int j = 0; j < 4; j++) acc[i][j] += kk[i] * vv[j];
        }
        __syncthreads();
    }

    float* kvout = g_kv + (size_t)bh * HD * HD;
#pragma unroll
    for (int i = 0; i < 4; i++)
#pragma unroll
        for (int j = 0; j < 4; j++)
            atomicAdd(&kvout[(d0 + i) * 64 + e0 + j], acc[i][j]);
    if (tid < 64) atomicAdd(&g_km[bh * 64 + tid], kmacc);
}

// ---------------- res[t,e] = z[t] * sum_d rope(q)[t,d]*kv[d,e]; y = (res+lepe)*gate ----------------
__global__ void __launch_bounds__(256) res_kernel(
    const float* __restrict__ sinp, const float* __restrict__ cosp)
{
    const int bh = blockIdx.x;
    const int b = bh >> 3, h = bh & 7;
    const int tid = threadIdx.x;
    const int t = blockIdx.y * 256 + tid;
    const float* Q = g_qkvo + ((size_t)b * 2048 + h * 64) * NT;

    __shared__ float skv[64][64];
    __shared__ float skm[64];
#pragma unroll
    for (int r = 0; r < 16; r++)
        ((float*)skv)[tid + r * 256] = g_kv[(size_t)bh * 4096 + tid + r * 256];
    if (tid < 64) skm[tid] = g_km[bh * 64 + tid];
    __syncthreads();

    float res[64];
#pragma unroll
    for (int e = 0; e < 64; e++) res[e] = 0.f;
    float zacc = 0.f;

    for (int p = 0; p < 32; p++) {
        const int d = 2 * p;
        float q0 = elu1(Q[(size_t)d * NT + t]);
        float q1 = elu1(Q[(size_t)(d + 1) * NT + t]);
        zacc += q0 * skm[d] + q1 * skm[d + 1];
        float c0 = cosp[t * 64 + d],     s0 = sinp[t * 64 + d];
        float c1 = cosp[t * 64 + d + 1], s1 = sinp[t * 64 + d + 1];
        float qr0 = q0 * c0 - q1 * s0;
        float qr1 = q1 * c1 + q0 * s1;
        const float4* kv0 = (const float4*)skv[d];
        const float4* kv1 = (const float4*)skv[d + 1];
#pragma unroll
        for (int e4 = 0; e4 < 16; e4++) {
            float4 a = kv0[e4], bb = kv1[e4];
            res[e4 * 4 + 0] += qr0 * a.x + qr1 * bb.x;
            res[e4 * 4 + 1] += qr0 * a.y + qr1 * bb.y;
            res[e4 * 4 + 2] += qr0 * a.z + qr1 * bb.z;
            res[e4 * 4 + 3] += qr0 * a.w + qr1 * bb.w;
        }
    }
    const float z = 1.f / (zacc + 1e-6f);

#pragma unroll 8
    for (int e = 0; e < 64; e++) {
        int c = h * 64 + e;
        size_t idx = ((size_t)b * 512 + c) * NT + t;
        float gate = g_qkvo[((size_t)b * 2048 + 1536 + c) * NT + t];
        g_y[idx] = (res[e] * z + g_lepe[idx]) * gate;
    }
}

// ---------------- launch ----------------
extern "C" void kernel_launch(void* const* d_in, const int* in_sizes, int n_in,
                              void* d_out, int out_size)
{
    const float* x      = (const float*)d_in[0];
    const float* sinp   = (const float*)d_in[1];
    const float* cosp   = (const float*)d_in[2];
    const float* w_qkvo = (const float*)d_in[3];
    const float* b_qkvo = (const float*)d_in[4];
    const float* w_lepe = (const float*)d_in[5];
    const float* b_lepe = (const float*)d_in[6];
    const float* w_proj = (const float*)d_in[7];
    const float* b_proj = (const float*)d_in[8];
    float* out = (float*)d_out;

    float *qkvo_p = nullptr, *y_p = nullptr;
    cudaGetSymbolAddress((void**)&qkvo_p, g_qkvo);
    cudaGetSymbolAddress((void**)&y_p,    g_y);

    zero_kernel<<<(NB * NHEADS * HD * HD + 255) / 256, 256>>>();

    dim3 g1(NT / 128, 2048 / 128, NB);
    gemm_bias_kernel<<<g1, 256>>>(w_qkvo, x, b_qkvo, qkvo_p, 2048, 512, NT);

    conv_kernel<<<dim3(NB * CDIM, 16), 256>>>(w_lepe, b_lepe);

    stats_kernel<<<NB * NHEADS, 256>>>();

    kv_kernel<<<dim3(NB * NHEADS, 8), 256>>>(sinp, cosp);

    res_kernel<<<dim3(NB * NHEADS, 16), 256>>>(sinp, cosp);

    dim3 g2(NT / 128, 512 / 128, NB);
    gemm_bias_kernel<<<g2, 256>>>(w_proj, y_p, b_proj, out, 512, 512, NT);
}